// round 4
// baseline (speedup 1.0000x reference)
#include <cuda_runtime.h>
#include <cuda_bf16.h>

#define GN 100000
#define GE 1600000
#define EPS 1e-5f

// ---------------- scratch (static device globals; no runtime alloc) --------
__device__ float g_bufA[GN * 64];
__device__ float g_bufB[GN * 64];
__device__ float g_out_isqrt[GN];
__device__ float g_in_isqrt[GN];
__device__ float g_stats[256];   // [0:64) sum, [64:128) sumsq, [128:192) scale, [192:256) shift

// ---------------- zero helpers ----------------
__global__ void k_zero_deg() {
    int i = blockIdx.x * blockDim.x + threadIdx.x;
    if (i < GN) { g_out_isqrt[i] = 0.0f; g_in_isqrt[i] = 0.0f; }
}

__global__ void k_zero_buf(int which, int n) {
    int i = blockIdx.x * blockDim.x + threadIdx.x;
    if (i < n) {
        if (which == 0) g_bufA[i] = 0.0f;
        else            g_bufB[i] = 0.0f;
    }
}

__global__ void k_zero_out(float* p, int n) {
    int i = blockIdx.x * blockDim.x + threadIdx.x;
    if (i < n) p[i] = 0.0f;
}

__global__ void k_zero_stats() {
    if (threadIdx.x < 256) g_stats[threadIdx.x] = 0.0f;
}

// ---------------- degrees (src/dst are int32) ----------------
__global__ void k_degree(const int* __restrict__ src,
                         const int* __restrict__ dst) {
    int e = blockIdx.x * blockDim.x + threadIdx.x;
    if (e >= GE) return;
    int s = __ldg(&src[e]);
    int d = __ldg(&dst[e]);
    if ((unsigned)s < GN) atomicAdd(&g_out_isqrt[s], 1.0f);
    if ((unsigned)d < GN) atomicAdd(&g_in_isqrt[d], 1.0f);
}

__global__ void k_isqrt() {
    int i = blockIdx.x * blockDim.x + threadIdx.x;
    if (i >= GN) return;
    g_out_isqrt[i] = rsqrtf(fmaxf(g_out_isqrt[i], 1.0f));
    g_in_isqrt[i]  = rsqrtf(fmaxf(g_in_isqrt[i], 1.0f));
}

// ---------------- GEMM0: (features * out_isqrt) @ W0  [128 -> 64] -> bufA --
__global__ void k_gemm0(const float* __restrict__ feat,
                        const float* __restrict__ W) {
    __shared__ float sf[32][128];
    int base = blockIdx.x * 32;
    for (int i = threadIdx.x; i < 32 * 128; i += 256) {
        int nn = i >> 7, k = i & 127;
        int node = base + nn;
        float v = 0.0f;
        if (node < GN) v = feat[node * 128 + k] * g_out_isqrt[node];
        sf[nn][k] = v;
    }
    __syncthreads();
    int j = threadIdx.x & 31;
    int g = threadIdx.x >> 5;   // 0..7
    float acc[4][2] = {};
    #pragma unroll 4
    for (int k = 0; k < 128; k++) {
        float w0 = __ldg(&W[k * 64 + j]);
        float w1 = __ldg(&W[k * 64 + j + 32]);
        #pragma unroll
        for (int i = 0; i < 4; i++) {
            float f = sf[g + 8 * i][k];   // warp broadcast
            acc[i][0] += f * w0;
            acc[i][1] += f * w1;
        }
    }
    #pragma unroll
    for (int i = 0; i < 4; i++) {
        int node = base + g + 8 * i;
        if (node < GN) {
            g_bufA[node * 64 + j]      = acc[i][0];
            g_bufA[node * 64 + j + 32] = acc[i][1];
        }
    }
}

// ---------------- scatter-add, 64 features, warp per edge ----------------
// dir==0: bufA -> bufB ; dir==1: bufB -> bufA
__global__ void k_scatter64(const int* __restrict__ src,
                            const int* __restrict__ dst,
                            int dir) {
    int warp = (blockIdx.x * blockDim.x + threadIdx.x) >> 5;
    int lane = threadIdx.x & 31;
    if (warp >= GE) return;
    int s = __ldg(&src[warp]);
    int d = __ldg(&dst[warp]);
    if ((unsigned)s >= GN || (unsigned)d >= GN) return;
    const float* in  = dir ? g_bufB : g_bufA;
    float*       out = dir ? g_bufA : g_bufB;
    const float* ip = in + (size_t)s * 64;
    float* op = out + (size_t)d * 64;
    atomicAdd(op + lane,      ip[lane]);
    atomicAdd(op + lane + 32, ip[lane + 32]);
}

// ---------------- post layer0: y = bufB*in_isqrt + b -> bufA; BN stats ----
__global__ void k_post_stats(const float* __restrict__ bias) {
    __shared__ float ssum[256], ssq[256];
    int f = threadIdx.x & 63;
    float b = __ldg(&bias[f]);
    int base = blockIdx.x * 64;
    float sum = 0.0f, sq = 0.0f;
    #pragma unroll
    for (int i = 0; i < 16; i++) {
        int idx = base * 64 + i * 256 + threadIdx.x;
        int node = idx >> 6;
        if (node < GN) {
            float v = g_bufB[idx] * g_in_isqrt[node] + b;
            g_bufA[idx] = v;
            sum += v; sq += v * v;
        }
    }
    ssum[threadIdx.x] = sum; ssq[threadIdx.x] = sq;
    __syncthreads();
    if (threadIdx.x < 64) {
        float s = ssum[threadIdx.x] + ssum[threadIdx.x + 64] +
                  ssum[threadIdx.x + 128] + ssum[threadIdx.x + 192];
        float q = ssq[threadIdx.x] + ssq[threadIdx.x + 64] +
                  ssq[threadIdx.x + 128] + ssq[threadIdx.x + 192];
        atomicAdd(&g_stats[threadIdx.x], s);
        atomicAdd(&g_stats[64 + threadIdx.x], q);
    }
}

// ---------------- finalize BN ----------------
__global__ void k_finalize_bn(const float* __restrict__ gamma,
                              const float* __restrict__ beta) {
    int f = threadIdx.x;
    if (f >= 64) return;
    float inv_n = 1.0f / (float)GN;
    float mu = g_stats[f] * inv_n;
    float var = g_stats[64 + f] * inv_n - mu * mu;
    float rstd = rsqrtf(var + EPS);
    float sc = __ldg(&gamma[f]) * rstd;
    g_stats[128 + f] = sc;
    g_stats[192 + f] = __ldg(&beta[f]) - mu * sc;
}

// ---------------- apply BN + ReLU + pre-scale by out_isqrt ----------------
// dir==0: bufA -> bufB ; dir==1: bufB -> bufA
__global__ void k_bn_relu_scale(int dir) {
    int idx = blockIdx.x * blockDim.x + threadIdx.x;
    if (idx >= GN * 64) return;
    int f = idx & 63, n = idx >> 6;
    float x = dir ? g_bufB[idx] : g_bufA[idx];
    float v = g_stats[128 + f] * x + g_stats[192 + f];
    v = fmaxf(v, 0.0f);
    v *= g_out_isqrt[n];
    if (dir) g_bufA[idx] = v;
    else     g_bufB[idx] = v;
}

// ---------------- GEMM1: bufA @ W1 then *in_isqrt + b1 -> bufB; BN stats --
__global__ void k_gemm1_stats(const float* __restrict__ W,
                              const float* __restrict__ bias) {
    __shared__ float sf[32][64];
    __shared__ float ssum[512], ssq[512];
    int base = blockIdx.x * 32;
    for (int i = threadIdx.x; i < 32 * 64; i += 256) {
        int nn = i >> 6, k = i & 63;
        int node = base + nn;
        sf[nn][k] = (node < GN) ? g_bufA[node * 64 + k] : 0.0f;
    }
    __syncthreads();
    int j = threadIdx.x & 31;
    int g = threadIdx.x >> 5;
    float acc[4][2] = {};
    #pragma unroll 4
    for (int k = 0; k < 64; k++) {
        float w0 = __ldg(&W[k * 64 + j]);
        float w1 = __ldg(&W[k * 64 + j + 32]);
        #pragma unroll
        for (int i = 0; i < 4; i++) {
            float f = sf[g + 8 * i][k];
            acc[i][0] += f * w0;
            acc[i][1] += f * w1;
        }
    }
    float b0v = __ldg(&bias[j]), b1v = __ldg(&bias[j + 32]);
    float s0 = 0, q0 = 0, s1 = 0, q1 = 0;
    #pragma unroll
    for (int i = 0; i < 4; i++) {
        int node = base + g + 8 * i;
        if (node < GN) {
            float is = g_in_isqrt[node];
            float v0 = acc[i][0] * is + b0v;
            float v1 = acc[i][1] * is + b1v;
            g_bufB[node * 64 + j]      = v0;
            g_bufB[node * 64 + j + 32] = v1;
            s0 += v0; q0 += v0 * v0;
            s1 += v1; q1 += v1 * v1;
        }
    }
    ssum[threadIdx.x] = s0;       ssq[threadIdx.x] = q0;
    ssum[256 + threadIdx.x] = s1; ssq[256 + threadIdx.x] = q1;
    __syncthreads();
    if (threadIdx.x < 64) {
        int f = threadIdx.x;
        int off = (f < 32) ? f : 256 + (f - 32);
        float s = 0, q = 0;
        #pragma unroll
        for (int t = 0; t < 8; t++) { s += ssum[off + t * 32]; q += ssq[off + t * 32]; }
        atomicAdd(&g_stats[f], s);
        atomicAdd(&g_stats[64 + f], q);
    }
}

// ---------------- GEMM2: bufA @ W2  [64 -> 47] -> bufB (stride 64) --------
__global__ void k_gemm2(const float* __restrict__ W) {
    __shared__ float sf[16][64];
    int base = blockIdx.x * 16;
    for (int i = threadIdx.x; i < 16 * 64; i += 256) {
        int nn = i >> 6, k = i & 63;
        int node = base + nn;
        sf[nn][k] = (node < GN) ? g_bufA[node * 64 + k] : 0.0f;
    }
    __syncthreads();
    int j = threadIdx.x & 63;
    int g = threadIdx.x >> 6;   // 0..3
    if (j >= 47) return;
    float acc[4] = {};
    #pragma unroll 4
    for (int k = 0; k < 64; k++) {
        float w = __ldg(&W[k * 47 + j]);
        #pragma unroll
        for (int i = 0; i < 4; i++) acc[i] += sf[g + 4 * i][k] * w;
    }
    #pragma unroll
    for (int i = 0; i < 4; i++) {
        int node = base + g + 4 * i;
        if (node < GN) g_bufB[node * 64 + j] = acc[i];
    }
}

// ---------------- scatter-add, 47 features (bufB stride 64 -> out 47) -----
__global__ void k_scatter47(const int* __restrict__ src,
                            const int* __restrict__ dst,
                            float* __restrict__ out) {
    int warp = (blockIdx.x * blockDim.x + threadIdx.x) >> 5;
    int lane = threadIdx.x & 31;
    if (warp >= GE) return;
    int s = __ldg(&src[warp]);
    int d = __ldg(&dst[warp]);
    if ((unsigned)s >= GN || (unsigned)d >= GN) return;
    const float* ip = g_bufB + (size_t)s * 64;
    float* op = out + (size_t)d * 47;
    atomicAdd(op + lane, ip[lane]);
    if (lane < 15) atomicAdd(op + lane + 32, ip[lane + 32]);
}

// ---------------- final: out = out*in_isqrt + b2 ----------------
__global__ void k_final2(float* __restrict__ out, const float* __restrict__ b2) {
    int idx = blockIdx.x * blockDim.x + threadIdx.x;
    if (idx >= GN * 47) return;
    int n = idx / 47;
    int f = idx - n * 47;
    out[idx] = out[idx] * g_in_isqrt[n] + __ldg(&b2[f]);
}

// ============================================================================
extern "C" void kernel_launch(void* const* d_in, const int* in_sizes, int n_in,
                              void* d_out, int out_size) {
    const float* feat = (const float*)d_in[0];
    const int*   src  = (const int*)d_in[1];    // int32 (jax x64 disabled)
    const int*   dst  = (const int*)d_in[2];
    const float* W0 = (const float*)d_in[3];
    const float* b0 = (const float*)d_in[4];
    const float* W1 = (const float*)d_in[5];
    const float* b1 = (const float*)d_in[6];
    const float* W2 = (const float*)d_in[7];
    const float* b2 = (const float*)d_in[8];
    const float* gamma0 = (const float*)d_in[9];
    const float* beta0  = (const float*)d_in[10];
    const float* gamma1 = (const float*)d_in[11];
    const float* beta1  = (const float*)d_in[12];
    float* out = (float*)d_out;

    const int NF = GN * 64;
    const int SCATTER_BLOCKS = (int)(((long long)GE * 32 + 255) / 256);

    // degrees -> isqrt
    k_zero_deg<<<(GN + 255) / 256, 256>>>();
    k_degree<<<(GE + 255) / 256, 256>>>(src, dst);
    k_isqrt<<<(GN + 255) / 256, 256>>>();

    // ---- layer 0: matmul first (128 -> 64), then aggregate ----
    k_gemm0<<<(GN + 31) / 32, 256>>>(feat, W0);               // -> bufA
    k_zero_buf<<<(NF + 255) / 256, 256>>>(1, NF);             // bufB = 0
    k_scatter64<<<SCATTER_BLOCKS, 256>>>(src, dst, 0);        // A -> B
    k_zero_stats<<<1, 256>>>();
    k_post_stats<<<(GN + 63) / 64, 256>>>(b0);                // B -> A (+stats)
    k_finalize_bn<<<1, 64>>>(gamma0, beta0);
    k_bn_relu_scale<<<(NF + 255) / 256, 256>>>(0);            // A -> B (= hs)

    // ---- layer 1: aggregate first, then matmul (64 -> 64) ----
    k_zero_buf<<<(NF + 255) / 256, 256>>>(0, NF);             // bufA = 0
    k_scatter64<<<SCATTER_BLOCKS, 256>>>(src, dst, 1);        // B -> A
    k_zero_stats<<<1, 256>>>();
    k_gemm1_stats<<<(GN + 31) / 32, 256>>>(W1, b1);           // A -> B (+stats)
    k_finalize_bn<<<1, 64>>>(gamma1, beta1);
    k_bn_relu_scale<<<(NF + 255) / 256, 256>>>(1);            // B -> A (= hs2)

    // ---- layer 2: matmul first (64 -> 47), then aggregate ----
    k_gemm2<<<(GN + 15) / 16, 256>>>(W2);                     // A -> B (stride 64)
    k_zero_out<<<(GN * 47 + 255) / 256, 256>>>(out, GN * 47);
    k_scatter47<<<SCATTER_BLOCKS, 256>>>(src, dst, out);      // B -> out
    k_final2<<<(GN * 47 + 255) / 256, 256>>>(out, b2);
}

// round 7
// speedup vs baseline: 2.1831x; 2.1831x over previous
#include <cuda_runtime.h>
#include <cuda_bf16.h>

#define GN 100000
#define GE 1600000
#define EPS 1e-5f
#define NB_SCAN 98   // ceil(GN/1024)

// ---------------- scratch (static device globals; no runtime alloc) --------
__device__ float g_bufA[GN * 64];
__device__ float g_bufB[GN * 64];
__device__ float g_out_isqrt[GN];
__device__ float g_in_isqrt[GN];
__device__ float g_stats[256];   // [0:64) sum, [64:128) sumsq, [128:192) scale, [192:256) shift
__device__ int   g_cnt_in[GN];
__device__ int   g_cnt_out[GN];
__device__ int   g_row[GN + 1];
__device__ int   g_col[GE];
__device__ int   g_fill[GN];
__device__ int   g_bsum[128];

// ---------------- zero helpers ----------------
__global__ void k_zero_int() {
    int i = blockIdx.x * blockDim.x + threadIdx.x;
    if (i < GN) { g_cnt_in[i] = 0; g_cnt_out[i] = 0; g_fill[i] = 0; }
}

__global__ void k_zero_stats() {
    if (threadIdx.x < 256) g_stats[threadIdx.x] = 0.0f;
}

// ---------------- degree counts (src/dst are int32) ----------------
__global__ void k_count(const int* __restrict__ src,
                        const int* __restrict__ dst) {
    int e = blockIdx.x * blockDim.x + threadIdx.x;
    if (e >= GE) return;
    int s = __ldg(&src[e]);
    int d = __ldg(&dst[e]);
    if ((unsigned)s < GN) atomicAdd(&g_cnt_out[s], 1);
    if ((unsigned)d < GN) atomicAdd(&g_cnt_in[d], 1);
}

__global__ void k_isqrt() {
    int i = blockIdx.x * blockDim.x + threadIdx.x;
    if (i >= GN) return;
    g_out_isqrt[i] = rsqrtf(fmaxf((float)g_cnt_out[i], 1.0f));
    g_in_isqrt[i]  = rsqrtf(fmaxf((float)g_cnt_in[i], 1.0f));
}

// ---------------- CSR build: scan of g_cnt_in -> g_row, fill g_col --------
__global__ void k_scan_part() {
    __shared__ int red[1024];
    int gid = blockIdx.x * 1024 + threadIdx.x;
    int v = (gid < GN) ? g_cnt_in[gid] : 0;
    red[threadIdx.x] = v;
    __syncthreads();
    for (int s = 512; s > 0; s >>= 1) {
        if (threadIdx.x < s) red[threadIdx.x] += red[threadIdx.x + s];
        __syncthreads();
    }
    if (threadIdx.x == 0) g_bsum[blockIdx.x] = red[0];
}

__global__ void k_scan_mid() {
    if (threadIdx.x != 0) return;
    int run = 0;
    for (int b = 0; b < NB_SCAN; b++) {
        int t = g_bsum[b];
        g_bsum[b] = run;
        run += t;
    }
    g_row[GN] = run;
}

__global__ void k_scan_final() {
    __shared__ int s[1024];
    int gid = blockIdx.x * 1024 + threadIdx.x;
    int v = (gid < GN) ? g_cnt_in[gid] : 0;
    s[threadIdx.x] = v;
    __syncthreads();
    for (int off = 1; off < 1024; off <<= 1) {
        int t = (threadIdx.x >= off) ? s[threadIdx.x - off] : 0;
        __syncthreads();
        s[threadIdx.x] += t;
        __syncthreads();
    }
    if (gid < GN) g_row[gid] = s[threadIdx.x] - v + g_bsum[blockIdx.x];
}

__global__ void k_fill(const int* __restrict__ src,
                       const int* __restrict__ dst) {
    int e = blockIdx.x * blockDim.x + threadIdx.x;
    if (e >= GE) return;
    int s = __ldg(&src[e]);
    int d = __ldg(&dst[e]);
    if ((unsigned)s >= GN || (unsigned)d >= GN) return;
    int pos = g_row[d] + atomicAdd(&g_fill[d], 1);
    g_col[pos] = s;
}

// ---------------- GEMM0: (features * out_isqrt) @ W0  [128 -> 64] -> bufA --
// 64 nodes x 64 cols per block; thread = 4 nodes x 4 cols; W staged in 32-row panels
__global__ void k_gemm0(const float* __restrict__ feat,
                        const float* __restrict__ W) {
    __shared__ float sA[64][132];
    __shared__ float sW[32][64];
    int base = blockIdx.x * 64;
    for (int i = threadIdx.x; i < 64 * 128; i += 256) {
        int n = i >> 7, k = i & 127;
        int node = base + n;
        float v = 0.0f;
        if (node < GN) v = feat[node * 128 + k] * g_out_isqrt[node];
        sA[n][k] = v;
    }
    int ng = (threadIdx.x >> 4) * 4;   // node group 0..60
    int cg = (threadIdx.x & 15) * 4;   // col group 0..60
    float acc[4][4] = {};
    for (int kb = 0; kb < 4; kb++) {
        __syncthreads();
        for (int i = threadIdx.x; i < 32 * 64; i += 256) {
            int kk = i >> 6, c = i & 63;
            sW[kk][c] = __ldg(&W[(kb * 32 + kk) * 64 + c]);
        }
        __syncthreads();
        #pragma unroll
        for (int kk = 0; kk < 32; kk++) {
            float4 w = *(const float4*)&sW[kk][cg];
            int k = kb * 32 + kk;
            #pragma unroll
            for (int i = 0; i < 4; i++) {
                float a = sA[ng + i][k];
                acc[i][0] += a * w.x; acc[i][1] += a * w.y;
                acc[i][2] += a * w.z; acc[i][3] += a * w.w;
            }
        }
    }
    #pragma unroll
    for (int i = 0; i < 4; i++) {
        int node = base + ng + i;
        if (node < GN)
            *(float4*)&g_bufA[node * 64 + cg] =
                make_float4(acc[i][0], acc[i][1], acc[i][2], acc[i][3]);
    }
}

// ---------------- gather, 64 feats, layer0 epilogue fused (isqrt+bias+BN stats)
// bufA -> bufB
__global__ void k_gather64_l0(const float* __restrict__ bias) {
    __shared__ float s_s[64], s_q[64];
    if (threadIdx.x < 64) { s_s[threadIdx.x] = 0.0f; s_q[threadIdx.x] = 0.0f; }
    __syncthreads();
    int node = blockIdx.x * 8 + (threadIdx.x >> 5);
    int lane = threadIdx.x & 31;
    if (node < GN) {
        int beg = g_row[node], end = g_row[node + 1];
        float ax = 0.0f, ay = 0.0f;
        for (int e = beg; e < end; e++) {
            int s = __ldg(&g_col[e]);
            float2 v = *(const float2*)&g_bufA[s * 64 + 2 * lane];
            ax += v.x; ay += v.y;
        }
        float isq = g_in_isqrt[node];
        float v0 = ax * isq + __ldg(&bias[2 * lane]);
        float v1 = ay * isq + __ldg(&bias[2 * lane + 1]);
        *(float2*)&g_bufB[node * 64 + 2 * lane] = make_float2(v0, v1);
        atomicAdd(&s_s[2 * lane], v0);     atomicAdd(&s_s[2 * lane + 1], v1);
        atomicAdd(&s_q[2 * lane], v0 * v0); atomicAdd(&s_q[2 * lane + 1], v1 * v1);
    }
    __syncthreads();
    if (threadIdx.x < 64) {
        atomicAdd(&g_stats[threadIdx.x],      s_s[threadIdx.x]);
        atomicAdd(&g_stats[64 + threadIdx.x], s_q[threadIdx.x]);
    }
}

// ---------------- gather, 64 feats, plain: bufA -> bufB ----------------
__global__ void k_gather64() {
    int node = blockIdx.x * 8 + (threadIdx.x >> 5);
    int lane = threadIdx.x & 31;
    if (node >= GN) return;
    int beg = g_row[node], end = g_row[node + 1];
    float ax = 0.0f, ay = 0.0f;
    for (int e = beg; e < end; e++) {
        int s = __ldg(&g_col[e]);
        float2 v = *(const float2*)&g_bufA[s * 64 + 2 * lane];
        ax += v.x; ay += v.y;
    }
    *(float2*)&g_bufB[node * 64 + 2 * lane] = make_float2(ax, ay);
}

// ---------------- finalize BN ----------------
__global__ void k_finalize_bn(const float* __restrict__ gamma,
                              const float* __restrict__ beta) {
    int f = threadIdx.x;
    if (f >= 64) return;
    float inv_n = 1.0f / (float)GN;
    float mu = g_stats[f] * inv_n;
    float var = g_stats[64 + f] * inv_n - mu * mu;
    float rstd = rsqrtf(var + EPS);
    float sc = __ldg(&gamma[f]) * rstd;
    g_stats[128 + f] = sc;
    g_stats[192 + f] = __ldg(&beta[f]) - mu * sc;
}

// ---------------- BN + ReLU + pre-scale by out_isqrt ----------------
// dir==0: bufA -> bufB ; dir==1: bufB -> bufA
__global__ void k_bn_relu_scale(int dir) {
    int idx = blockIdx.x * blockDim.x + threadIdx.x;
    if (idx >= GN * 64) return;
    int f = idx & 63, n = idx >> 6;
    float x = dir ? g_bufB[idx] : g_bufA[idx];
    float v = g_stats[128 + f] * x + g_stats[192 + f];
    v = fmaxf(v, 0.0f);
    v *= g_out_isqrt[n];
    if (dir) g_bufA[idx] = v;
    else     g_bufB[idx] = v;
}

// ---------------- GEMM1: bufB @ W1 then *in_isqrt + b1 -> bufA; BN stats --
__global__ void k_gemm1_stats(const float* __restrict__ W,
                              const float* __restrict__ bias) {
    __shared__ float sf[32][64];
    __shared__ float ssum[512], ssq[512];
    int base = blockIdx.x * 32;
    for (int i = threadIdx.x; i < 32 * 64; i += 256) {
        int nn = i >> 6, k = i & 63;
        int node = base + nn;
        sf[nn][k] = (node < GN) ? g_bufB[node * 64 + k] : 0.0f;
    }
    __syncthreads();
    int j = threadIdx.x & 31;
    int g = threadIdx.x >> 5;
    float acc[4][2] = {};
    #pragma unroll 4
    for (int k = 0; k < 64; k++) {
        float w0 = __ldg(&W[k * 64 + j]);
        float w1 = __ldg(&W[k * 64 + j + 32]);
        #pragma unroll
        for (int i = 0; i < 4; i++) {
            float f = sf[g + 8 * i][k];
            acc[i][0] += f * w0;
            acc[i][1] += f * w1;
        }
    }
    float b0v = __ldg(&bias[j]), b1v = __ldg(&bias[j + 32]);
    float s0 = 0, q0 = 0, s1 = 0, q1 = 0;
    #pragma unroll
    for (int i = 0; i < 4; i++) {
        int node = base + g + 8 * i;
        if (node < GN) {
            float is = g_in_isqrt[node];
            float v0 = acc[i][0] * is + b0v;
            float v1 = acc[i][1] * is + b1v;
            g_bufA[node * 64 + j]      = v0;
            g_bufA[node * 64 + j + 32] = v1;
            s0 += v0; q0 += v0 * v0;
            s1 += v1; q1 += v1 * v1;
        }
    }
    ssum[threadIdx.x] = s0;       ssq[threadIdx.x] = q0;
    ssum[256 + threadIdx.x] = s1; ssq[256 + threadIdx.x] = q1;
    __syncthreads();
    if (threadIdx.x < 64) {
        int f = threadIdx.x;
        int off = (f < 32) ? f : 256 + (f - 32);
        float s = 0, q = 0;
        #pragma unroll
        for (int t = 0; t < 8; t++) { s += ssum[off + t * 32]; q += ssq[off + t * 32]; }
        atomicAdd(&g_stats[f], s);
        atomicAdd(&g_stats[64 + f], q);
    }
}

// ---------------- GEMM2: bufB @ W2  [64 -> 47] -> bufA (stride 64) --------
__global__ void k_gemm2(const float* __restrict__ W) {
    __shared__ float sf[16][64];
    int base = blockIdx.x * 16;
    for (int i = threadIdx.x; i < 16 * 64; i += 256) {
        int nn = i >> 6, k = i & 63;
        int node = base + nn;
        sf[nn][k] = (node < GN) ? g_bufB[node * 64 + k] : 0.0f;
    }
    __syncthreads();
    int j = threadIdx.x & 63;
    int g = threadIdx.x >> 6;   // 0..3
    if (j >= 47) return;
    float acc[4] = {};
    #pragma unroll 4
    for (int k = 0; k < 64; k++) {
        float w = __ldg(&W[k * 47 + j]);
        #pragma unroll
        for (int i = 0; i < 4; i++) acc[i] += sf[g + 4 * i][k] * w;
    }
    #pragma unroll
    for (int i = 0; i < 4; i++) {
        int node = base + g + 4 * i;
        if (node < GN) g_bufA[node * 64 + j] = acc[i];
    }
}

// ---------------- gather, 47 feats + final epilogue: bufA -> out ----------
__global__ void k_gather47(const float* __restrict__ b2,
                           float* __restrict__ out) {
    int node = blockIdx.x * 8 + (threadIdx.x >> 5);
    int lane = threadIdx.x & 31;
    if (node >= GN) return;
    int beg = g_row[node], end = g_row[node + 1];
    int f = 2 * lane;
    float ax = 0.0f, ay = 0.0f;
    if (f < 46) {                    // lanes 0..22: pair
        for (int e = beg; e < end; e++) {
            int s = __ldg(&g_col[e]);
            float2 v = *(const float2*)&g_bufA[s * 64 + f];
            ax += v.x; ay += v.y;
        }
        float isq = g_in_isqrt[node];
        out[node * 47 + f]     = ax * isq + __ldg(&b2[f]);
        out[node * 47 + f + 1] = ay * isq + __ldg(&b2[f + 1]);
    } else if (f == 46) {            // lane 23: single feat 46
        for (int e = beg; e < end; e++) {
            int s = __ldg(&g_col[e]);
            ax += g_bufA[s * 64 + 46];
        }
        out[node * 47 + 46] = ax * g_in_isqrt[node] + __ldg(&b2[46]);
    }
}

// ============================================================================
extern "C" void kernel_launch(void* const* d_in, const int* in_sizes, int n_in,
                              void* d_out, int out_size) {
    const float* feat = (const float*)d_in[0];
    const int*   src  = (const int*)d_in[1];    // int32 (jax x64 disabled)
    const int*   dst  = (const int*)d_in[2];
    const float* W0 = (const float*)d_in[3];
    const float* b0 = (const float*)d_in[4];
    const float* W1 = (const float*)d_in[5];
    const float* b1 = (const float*)d_in[6];
    const float* W2 = (const float*)d_in[7];
    const float* b2 = (const float*)d_in[8];
    const float* gamma0 = (const float*)d_in[9];
    const float* beta0  = (const float*)d_in[10];
    const float* gamma1 = (const float*)d_in[11];
    const float* beta1  = (const float*)d_in[12];
    float* out = (float*)d_out;

    const int NF = GN * 64;
    const int GB = 12500;  // gather blocks: 8 nodes each

    // ---- CSR build + degree isqrt ----
    k_zero_int<<<(GN + 255) / 256, 256>>>();
    k_count<<<(GE + 255) / 256, 256>>>(src, dst);
    k_isqrt<<<(GN + 255) / 256, 256>>>();
    k_scan_part<<<NB_SCAN, 1024>>>();
    k_scan_mid<<<1, 32>>>();
    k_scan_final<<<NB_SCAN, 1024>>>();
    k_fill<<<(GE + 255) / 256, 256>>>(src, dst);

    // ---- layer 0: matmul (128 -> 64), gather w/ fused epilogue ----
    k_gemm0<<<(GN + 63) / 64, 256>>>(feat, W0);           // feat -> bufA
    k_zero_stats<<<1, 256>>>();
    k_gather64_l0<<<GB, 256>>>(b0);                       // bufA -> bufB (+stats)
    k_finalize_bn<<<1, 64>>>(gamma0, beta0);
    k_bn_relu_scale<<<(NF + 255) / 256, 256>>>(1);        // bufB -> bufA (= hs)

    // ---- layer 1: gather, matmul (64 -> 64) ----
    k_gather64<<<GB, 256>>>();                            // bufA -> bufB
    k_zero_stats<<<1, 256>>>();
    k_gemm1_stats<<<(GN + 31) / 32, 256>>>(W1, b1);       // bufB -> bufA (+stats)
    k_finalize_bn<<<1, 64>>>(gamma1, beta1);
    k_bn_relu_scale<<<(NF + 255) / 256, 256>>>(0);        // bufA -> bufB (= hs2)

    // ---- layer 2: matmul (64 -> 47), gather w/ fused final ----
    k_gemm2<<<(GN + 15) / 16, 256>>>(W2);                 // bufB -> bufA (stride 64)
    k_gather47<<<GB, 256>>>(b2, out);                     // bufA -> out
}

// round 8
// speedup vs baseline: 2.3053x; 1.0560x over previous
#include <cuda_runtime.h>
#include <cuda_bf16.h>

#define GN 100000
#define GE 1600000
#define EPS 1e-5f
#define NB_SCAN 98   // ceil(GN/1024)

// ---------------- scratch (static device globals; no runtime alloc) --------
__device__ float g_bufA[GN * 64];
__device__ float g_bufB[GN * 64];
__device__ float g_out_isqrt[GN];
__device__ float g_in_isqrt[GN];
__device__ float g_stats[256];   // [0:64) sum, [64:128) sumsq, [128:192) scale, [192:256) shift
__device__ int   g_cnt_in[GN];
__device__ int   g_cnt_out[GN];
__device__ int   g_row[GN + 1];
__device__ int   g_col[GE];
__device__ int   g_fill[GN];     // initialized to row offsets by scan_final
__device__ int   g_bsum[128];

// ---------------- zero helpers ----------------
__global__ void k_zero_int() {
    int i = blockIdx.x * blockDim.x + threadIdx.x;
    if (i < GN) { g_cnt_in[i] = 0; g_cnt_out[i] = 0; }
}

__global__ void k_zero_stats() {
    if (threadIdx.x < 256) g_stats[threadIdx.x] = 0.0f;
}

// ---------------- degree counts (src/dst are int32) ----------------
__global__ void k_count(const int* __restrict__ src,
                        const int* __restrict__ dst) {
    int e = blockIdx.x * blockDim.x + threadIdx.x;
    if (e >= GE) return;
    int s = __ldg(&src[e]);
    int d = __ldg(&dst[e]);
    if ((unsigned)s < GN) atomicAdd(&g_cnt_out[s], 1);
    if ((unsigned)d < GN) atomicAdd(&g_cnt_in[d], 1);
}

__global__ void k_isqrt() {
    int i = blockIdx.x * blockDim.x + threadIdx.x;
    if (i >= GN) return;
    g_out_isqrt[i] = rsqrtf(fmaxf((float)g_cnt_out[i], 1.0f));
    g_in_isqrt[i]  = rsqrtf(fmaxf((float)g_cnt_in[i], 1.0f));
}

// ---------------- CSR build: scan of g_cnt_in -> g_row, fill g_col --------
__global__ void k_scan_part() {
    __shared__ int red[1024];
    int gid = blockIdx.x * 1024 + threadIdx.x;
    int v = (gid < GN) ? g_cnt_in[gid] : 0;
    red[threadIdx.x] = v;
    __syncthreads();
    for (int s = 512; s > 0; s >>= 1) {
        if (threadIdx.x < s) red[threadIdx.x] += red[threadIdx.x + s];
        __syncthreads();
    }
    if (threadIdx.x == 0) g_bsum[blockIdx.x] = red[0];
}

__global__ void k_scan_mid() {
    if (threadIdx.x != 0) return;
    int run = 0;
    for (int b = 0; b < NB_SCAN; b++) {
        int t = g_bsum[b];
        g_bsum[b] = run;
        run += t;
    }
    g_row[GN] = run;
}

__global__ void k_scan_final() {
    __shared__ int s[1024];
    int gid = blockIdx.x * 1024 + threadIdx.x;
    int v = (gid < GN) ? g_cnt_in[gid] : 0;
    s[threadIdx.x] = v;
    __syncthreads();
    for (int off = 1; off < 1024; off <<= 1) {
        int t = (threadIdx.x >= off) ? s[threadIdx.x - off] : 0;
        __syncthreads();
        s[threadIdx.x] += t;
        __syncthreads();
    }
    if (gid < GN) {
        int r = s[threadIdx.x] - v + g_bsum[blockIdx.x];
        g_row[gid]  = r;
        g_fill[gid] = r;   // fill cursor starts at row offset
    }
}

__global__ void k_fill(const int* __restrict__ src,
                       const int* __restrict__ dst) {
    int e = blockIdx.x * blockDim.x + threadIdx.x;
    if (e >= GE) return;
    int s = __ldg(&src[e]);
    int d = __ldg(&dst[e]);
    if ((unsigned)s >= GN || (unsigned)d >= GN) return;
    int pos = atomicAdd(&g_fill[d], 1);
    g_col[pos] = s;
}

// ---------------- GEMM0: (features * out_isqrt) @ W0  [128 -> 64] -> bufA --
// 64 nodes x 64 cols per block; thread = 4 nodes x 4 cols; float4 loads
__global__ void k_gemm0(const float* __restrict__ feat,
                        const float* __restrict__ W) {
    __shared__ float sA[64][132];
    __shared__ float sW[32][64];
    int base = blockIdx.x * 64;
    // load 64 x 128 tile with float4 (each thread 8 float4s)
    for (int i = threadIdx.x; i < 64 * 32; i += 256) {
        int n = i >> 5, k4 = i & 31;
        int node = base + n;
        float4 v = make_float4(0.f, 0.f, 0.f, 0.f);
        if (node < GN) {
            v = __ldg((const float4*)&feat[node * 128 + 4 * k4]);
            float sc = g_out_isqrt[node];
            v.x *= sc; v.y *= sc; v.z *= sc; v.w *= sc;
        }
        *(float4*)&sA[n][4 * k4] = v;
    }
    int ng = (threadIdx.x >> 4) * 4;   // node group 0..60
    int cg = (threadIdx.x & 15) * 4;   // col group 0..60
    float acc[4][4] = {};
    for (int kb = 0; kb < 4; kb++) {
        __syncthreads();
        for (int i = threadIdx.x; i < 32 * 16; i += 256) {
            int kk = i >> 4, c4 = i & 15;
            *(float4*)&sW[kk][4 * c4] = __ldg((const float4*)&W[(kb * 32 + kk) * 64 + 4 * c4]);
        }
        __syncthreads();
        #pragma unroll
        for (int kk = 0; kk < 32; kk++) {
            float4 w = *(const float4*)&sW[kk][cg];
            int k = kb * 32 + kk;
            #pragma unroll
            for (int i = 0; i < 4; i++) {
                float a = sA[ng + i][k];
                acc[i][0] += a * w.x; acc[i][1] += a * w.y;
                acc[i][2] += a * w.z; acc[i][3] += a * w.w;
            }
        }
    }
    #pragma unroll
    for (int i = 0; i < 4; i++) {
        int node = base + ng + i;
        if (node < GN)
            *(float4*)&g_bufA[node * 64 + cg] =
                make_float4(acc[i][0], acc[i][1], acc[i][2], acc[i][3]);
    }
}

// ---------------- gather, 64 feats, layer0 epilogue fused (isqrt+bias+BN stats)
// bufA -> bufB
__global__ void k_gather64_l0(const float* __restrict__ bias) {
    __shared__ float s_s[64], s_q[64];
    if (threadIdx.x < 64) { s_s[threadIdx.x] = 0.0f; s_q[threadIdx.x] = 0.0f; }
    __syncthreads();
    int node = blockIdx.x * 8 + (threadIdx.x >> 5);
    int lane = threadIdx.x & 31;
    if (node < GN) {
        int beg = g_row[node], end = g_row[node + 1];
        float ax = 0.0f, ay = 0.0f;
        for (int e = beg; e < end; e++) {
            int s = __ldg(&g_col[e]);
            float2 v = *(const float2*)&g_bufA[s * 64 + 2 * lane];
            ax += v.x; ay += v.y;
        }
        float isq = g_in_isqrt[node];
        float v0 = ax * isq + __ldg(&bias[2 * lane]);
        float v1 = ay * isq + __ldg(&bias[2 * lane + 1]);
        *(float2*)&g_bufB[node * 64 + 2 * lane] = make_float2(v0, v1);
        atomicAdd(&s_s[2 * lane], v0);      atomicAdd(&s_s[2 * lane + 1], v1);
        atomicAdd(&s_q[2 * lane], v0 * v0); atomicAdd(&s_q[2 * lane + 1], v1 * v1);
    }
    __syncthreads();
    if (threadIdx.x < 64) {
        atomicAdd(&g_stats[threadIdx.x],      s_s[threadIdx.x]);
        atomicAdd(&g_stats[64 + threadIdx.x], s_q[threadIdx.x]);
    }
}

// ---------------- finalize BN ----------------
__global__ void k_finalize_bn(const float* __restrict__ gamma,
                              const float* __restrict__ beta) {
    int f = threadIdx.x;
    if (f >= 64) return;
    float inv_n = 1.0f / (float)GN;
    float mu = g_stats[f] * inv_n;
    float var = g_stats[64 + f] * inv_n - mu * mu;
    float rstd = rsqrtf(var + EPS);
    float sc = __ldg(&gamma[f]) * rstd;
    g_stats[128 + f] = sc;
    g_stats[192 + f] = __ldg(&beta[f]) - mu * sc;
}

// ---------------- gather64 with fused BN+ReLU+out_isqrt on SOURCE elements
// reads y0 from bufB, applies t(x)=max(sc*x+sh,0)*out_isqrt[src], aggregates -> bufA
__global__ void k_gather64_bn() {
    int node = blockIdx.x * 8 + (threadIdx.x >> 5);
    int lane = threadIdx.x & 31;
    if (node >= GN) return;
    float sc0 = g_stats[128 + 2 * lane], sc1 = g_stats[128 + 2 * lane + 1];
    float sh0 = g_stats[192 + 2 * lane], sh1 = g_stats[192 + 2 * lane + 1];
    int beg = g_row[node], end = g_row[node + 1];
    float ax = 0.0f, ay = 0.0f;
    for (int e = beg; e < end; e++) {
        int s = __ldg(&g_col[e]);
        float os = __ldg(&g_out_isqrt[s]);
        float2 v = *(const float2*)&g_bufB[s * 64 + 2 * lane];
        ax += fmaxf(v.x * sc0 + sh0, 0.0f) * os;
        ay += fmaxf(v.y * sc1 + sh1, 0.0f) * os;
    }
    *(float2*)&g_bufA[node * 64 + 2 * lane] = make_float2(ax, ay);
}

// ---------------- GEMM1: bufA @ W1 then *in_isqrt + b1 -> bufB; BN stats --
__global__ void k_gemm1_stats(const float* __restrict__ W,
                              const float* __restrict__ bias) {
    __shared__ float sf[32][64];
    __shared__ float ssum[512], ssq[512];
    int base = blockIdx.x * 32;
    for (int i = threadIdx.x; i < 32 * 64; i += 256) {
        int nn = i >> 6, k = i & 63;
        int node = base + nn;
        sf[nn][k] = (node < GN) ? g_bufA[node * 64 + k] : 0.0f;
    }
    __syncthreads();
    int j = threadIdx.x & 31;
    int g = threadIdx.x >> 5;
    float acc[4][2] = {};
    #pragma unroll 4
    for (int k = 0; k < 64; k++) {
        float w0 = __ldg(&W[k * 64 + j]);
        float w1 = __ldg(&W[k * 64 + j + 32]);
        #pragma unroll
        for (int i = 0; i < 4; i++) {
            float f = sf[g + 8 * i][k];
            acc[i][0] += f * w0;
            acc[i][1] += f * w1;
        }
    }
    float b0v = __ldg(&bias[j]), b1v = __ldg(&bias[j + 32]);
    float s0 = 0, q0 = 0, s1 = 0, q1 = 0;
    #pragma unroll
    for (int i = 0; i < 4; i++) {
        int node = base + g + 8 * i;
        if (node < GN) {
            float is = g_in_isqrt[node];
            float v0 = acc[i][0] * is + b0v;
            float v1 = acc[i][1] * is + b1v;
            g_bufB[node * 64 + j]      = v0;
            g_bufB[node * 64 + j + 32] = v1;
            s0 += v0; q0 += v0 * v0;
            s1 += v1; q1 += v1 * v1;
        }
    }
    ssum[threadIdx.x] = s0;       ssq[threadIdx.x] = q0;
    ssum[256 + threadIdx.x] = s1; ssq[256 + threadIdx.x] = q1;
    __syncthreads();
    if (threadIdx.x < 64) {
        int f = threadIdx.x;
        int off = (f < 32) ? f : 256 + (f - 32);
        float s = 0, q = 0;
        #pragma unroll
        for (int t = 0; t < 8; t++) { s += ssum[off + t * 32]; q += ssq[off + t * 32]; }
        atomicAdd(&g_stats[f], s);
        atomicAdd(&g_stats[64 + f], q);
    }
}

// ---------------- GEMM2: t1(bufB) @ W2  [64 -> 47] -> bufA (stride 64) -----
// applies BN1+ReLU+out_isqrt transform during the smem load (once per element)
__global__ void k_gemm2_bn(const float* __restrict__ W) {
    __shared__ float sf[16][64];
    __shared__ float s_sc[64], s_sh[64];
    if (threadIdx.x < 64) {
        s_sc[threadIdx.x] = g_stats[128 + threadIdx.x];
        s_sh[threadIdx.x] = g_stats[192 + threadIdx.x];
    }
    __syncthreads();
    int base = blockIdx.x * 16;
    for (int i = threadIdx.x; i < 16 * 64; i += 256) {
        int nn = i >> 6, k = i & 63;
        int node = base + nn;
        float v = 0.0f;
        if (node < GN) {
            float x = g_bufB[node * 64 + k];
            v = fmaxf(x * s_sc[k] + s_sh[k], 0.0f) * g_out_isqrt[node];
        }
        sf[nn][k] = v;
    }
    __syncthreads();
    int j = threadIdx.x & 63;
    int g = threadIdx.x >> 6;   // 0..3
    if (j >= 47) return;
    float acc[4] = {};
    #pragma unroll 4
    for (int k = 0; k < 64; k++) {
        float w = __ldg(&W[k * 47 + j]);
        #pragma unroll
        for (int i = 0; i < 4; i++) acc[i] += sf[g + 4 * i][k] * w;
    }
    #pragma unroll
    for (int i = 0; i < 4; i++) {
        int node = base + g + 4 * i;
        if (node < GN) g_bufA[node * 64 + j] = acc[i];
    }
}

// ---------------- gather, 47 feats + final epilogue: bufA -> out ----------
__global__ void k_gather47(const float* __restrict__ b2,
                           float* __restrict__ out) {
    int node = blockIdx.x * 8 + (threadIdx.x >> 5);
    int lane = threadIdx.x & 31;
    if (node >= GN) return;
    int beg = g_row[node], end = g_row[node + 1];
    int f = 2 * lane;
    float ax = 0.0f, ay = 0.0f;
    if (f < 46) {                    // lanes 0..22: pair
        for (int e = beg; e < end; e++) {
            int s = __ldg(&g_col[e]);
            float2 v = *(const float2*)&g_bufA[s * 64 + f];
            ax += v.x; ay += v.y;
        }
        float isq = g_in_isqrt[node];
        out[node * 47 + f]     = ax * isq + __ldg(&b2[f]);
        out[node * 47 + f + 1] = ay * isq + __ldg(&b2[f + 1]);
    } else if (f == 46) {            // lane 23: single feat 46
        for (int e = beg; e < end; e++) {
            int s = __ldg(&g_col[e]);
            ax += g_bufA[s * 64 + 46];
        }
        out[node * 47 + 46] = ax * g_in_isqrt[node] + __ldg(&b2[46]);
    }
}

// ============================================================================
extern "C" void kernel_launch(void* const* d_in, const int* in_sizes, int n_in,
                              void* d_out, int out_size) {
    const float* feat = (const float*)d_in[0];
    const int*   src  = (const int*)d_in[1];    // int32 (jax x64 disabled)
    const int*   dst  = (const int*)d_in[2];
    const float* W0 = (const float*)d_in[3];
    const float* b0 = (const float*)d_in[4];
    const float* W1 = (const float*)d_in[5];
    const float* b1 = (const float*)d_in[6];
    const float* W2 = (const float*)d_in[7];
    const float* b2 = (const float*)d_in[8];
    const float* gamma0 = (const float*)d_in[9];
    const float* beta0  = (const float*)d_in[10];
    const float* gamma1 = (const float*)d_in[11];
    const float* beta1  = (const float*)d_in[12];
    float* out = (float*)d_out;

    const int GB = 12500;  // gather blocks: 8 nodes each

    // ---- CSR build + degree isqrt ----
    k_zero_int<<<(GN + 255) / 256, 256>>>();
    k_count<<<(GE + 255) / 256, 256>>>(src, dst);
    k_isqrt<<<(GN + 255) / 256, 256>>>();
    k_scan_part<<<NB_SCAN, 1024>>>();
    k_scan_mid<<<1, 32>>>();
    k_scan_final<<<NB_SCAN, 1024>>>();
    k_fill<<<(GE + 255) / 256, 256>>>(src, dst);

    // ---- layer 0: matmul (128 -> 64), gather w/ fused epilogue ----
    k_gemm0<<<(GN + 63) / 64, 256>>>(feat, W0);           // feat -> bufA
    k_zero_stats<<<1, 256>>>();
    k_gather64_l0<<<GB, 256>>>(b0);                       // bufA -> bufB (y0 + stats)
    k_finalize_bn<<<1, 64>>>(gamma0, beta0);

    // ---- layer 1: gather w/ fused BN0 transform, matmul (64 -> 64) ----
    k_gather64_bn<<<GB, 256>>>();                         // bufB -> bufA (agg of t0)
    k_zero_stats<<<1, 256>>>();
    k_gemm1_stats<<<(GN + 31) / 32, 256>>>(W1, b1);       // bufA -> bufB (y1 + stats)
    k_finalize_bn<<<1, 64>>>(gamma1, beta1);

    // ---- layer 2: matmul w/ fused BN1 transform (64 -> 47), gather ----
    k_gemm2_bn<<<(GN + 15) / 16, 256>>>(W2);              // bufB -> bufA (stride 64)
    k_gather47<<<GB, 256>>>(b2, out);                     // bufA -> out
}

// round 9
// speedup vs baseline: 2.6363x; 1.1436x over previous
#include <cuda_runtime.h>
#include <cuda_bf16.h>

#define GN 100000
#define GE 1600000
#define EPS 1e-5f
#define NB_SCAN 98   // ceil(GN/1024)

// ---------------- scratch (static device globals; no runtime alloc) --------
__device__ float g_bufA[GN * 64];
__device__ float g_bufB[GN * 64];
__device__ float g_out_isqrt[GN];
__device__ float g_in_isqrt[GN];
__device__ float g_stats[256];   // [0:64) sum, [64:128) sumsq, [128:192) scale, [192:256) shift
__device__ int   g_cnt_in[GN];
__device__ int   g_cnt_out[GN];
__device__ int   g_row[GN + 1];
__device__ int   g_col[GE];
__device__ int   g_fill[GN];
__device__ int   g_bsum[128];

// ---------------- zero helper ----------------
__global__ void k_zero_int() {
    int i = blockIdx.x * blockDim.x + threadIdx.x;
    if (i < GN) { g_cnt_in[i] = 0; g_cnt_out[i] = 0; }
}

// ---------------- degree counts (src/dst are int32) ----------------
__global__ void k_count(const int* __restrict__ src,
                        const int* __restrict__ dst) {
    int e = blockIdx.x * blockDim.x + threadIdx.x;
    if (e >= GE) return;
    int s = __ldg(&src[e]);
    int d = __ldg(&dst[e]);
    if ((unsigned)s < GN) atomicAdd(&g_cnt_out[s], 1);
    if ((unsigned)d < GN) atomicAdd(&g_cnt_in[d], 1);
}

// ---------------- CSR build: scan of g_cnt_in -> g_row, fill g_col --------
__global__ void k_scan_part() {
    __shared__ int red[1024];
    int gid = blockIdx.x * 1024 + threadIdx.x;
    int v = (gid < GN) ? g_cnt_in[gid] : 0;
    red[threadIdx.x] = v;
    __syncthreads();
    for (int s = 512; s > 0; s >>= 1) {
        if (threadIdx.x < s) red[threadIdx.x] += red[threadIdx.x + s];
        __syncthreads();
    }
    if (threadIdx.x == 0) g_bsum[blockIdx.x] = red[0];
}

__global__ void k_scan_mid() {
    if (threadIdx.x != 0) return;
    int run = 0;
    for (int b = 0; b < NB_SCAN; b++) {
        int t = g_bsum[b];
        g_bsum[b] = run;
        run += t;
    }
    g_row[GN] = run;
}

// scan_final + fused degree-isqrt
__global__ void k_scan_final() {
    __shared__ int s[1024];
    int gid = blockIdx.x * 1024 + threadIdx.x;
    int v = (gid < GN) ? g_cnt_in[gid] : 0;
    s[threadIdx.x] = v;
    __syncthreads();
    for (int off = 1; off < 1024; off <<= 1) {
        int t = (threadIdx.x >= off) ? s[threadIdx.x - off] : 0;
        __syncthreads();
        s[threadIdx.x] += t;
        __syncthreads();
    }
    if (gid < GN) {
        int r = s[threadIdx.x] - v + g_bsum[blockIdx.x];
        g_row[gid]  = r;
        g_fill[gid] = r;
        g_in_isqrt[gid]  = rsqrtf(fmaxf((float)v, 1.0f));
        g_out_isqrt[gid] = rsqrtf(fmaxf((float)g_cnt_out[gid], 1.0f));
    }
}

__global__ void k_fill(const int* __restrict__ src,
                       const int* __restrict__ dst) {
    int e = blockIdx.x * blockDim.x + threadIdx.x;
    if (e >= GE) return;
    int s = __ldg(&src[e]);
    int d = __ldg(&dst[e]);
    if ((unsigned)s >= GN || (unsigned)d >= GN) return;
    int pos = atomicAdd(&g_fill[d], 1);
    g_col[pos] = s;
}

// ---------------- GEMM0: (features * out_isqrt) @ W0  [128 -> 64] -> bufA --
// 128 nodes x 64 cols per block; thread = 8 nodes x 4 cols; A transposed in smem
__global__ void k_gemm0(const float* __restrict__ feat,
                        const float* __restrict__ W) {
    __shared__ float sAT[16][132];   // [k][node], pad 4
    __shared__ float sW[16][64];
    __shared__ float s_sc[128];
    int base = blockIdx.x * 128;
    for (int i = threadIdx.x; i < 128; i += 256) {
        int node = base + i;
        s_sc[i] = (node < GN) ? g_out_isqrt[node] : 0.0f;
    }
    // fold: zero BN stats accumulators (used by the next kernel)
    if (blockIdx.x == 0 && threadIdx.x < 128) g_stats[threadIdx.x] = 0.0f;
    int cgi = threadIdx.x & 15;      // col group: 4 cols
    int ngi = threadIdx.x >> 4;      // node group: 8 nodes
    int cg = cgi * 4;
    float acc[8][4] = {};
    for (int kb = 0; kb < 8; kb++) {
        __syncthreads();
        #pragma unroll
        for (int it = 0; it < 2; it++) {
            int task = threadIdx.x + 256 * it;   // 512 tasks: 128 nodes x 4 k4
            int node = task >> 2, k4 = task & 3;
            int gnode = base + node;
            float4 v = make_float4(0.f, 0.f, 0.f, 0.f);
            if (gnode < GN)
                v = __ldg((const float4*)&feat[gnode * 128 + kb * 16 + k4 * 4]);
            float sc = s_sc[node];
            sAT[4 * k4 + 0][node] = v.x * sc;
            sAT[4 * k4 + 1][node] = v.y * sc;
            sAT[4 * k4 + 2][node] = v.z * sc;
            sAT[4 * k4 + 3][node] = v.w * sc;
        }
        {
            int kk = threadIdx.x >> 4, c4 = threadIdx.x & 15;
            *(float4*)&sW[kk][c4 * 4] =
                __ldg((const float4*)&W[(kb * 16 + kk) * 64 + c4 * 4]);
        }
        __syncthreads();
        #pragma unroll
        for (int kk = 0; kk < 16; kk++) {
            float4 a0 = *(const float4*)&sAT[kk][ngi * 8];
            float4 a1 = *(const float4*)&sAT[kk][ngi * 8 + 4];
            float4 w  = *(const float4*)&sW[kk][cg];
            float av[8] = {a0.x, a0.y, a0.z, a0.w, a1.x, a1.y, a1.z, a1.w};
            #pragma unroll
            for (int i = 0; i < 8; i++) {
                acc[i][0] += av[i] * w.x;
                acc[i][1] += av[i] * w.y;
                acc[i][2] += av[i] * w.z;
                acc[i][3] += av[i] * w.w;
            }
        }
    }
    #pragma unroll
    for (int i = 0; i < 8; i++) {
        int node = base + ngi * 8 + i;
        if (node < GN)
            *(float4*)&g_bufA[node * 64 + cg] =
                make_float4(acc[i][0], acc[i][1], acc[i][2], acc[i][3]);
    }
}

// ---------------- gather, 64 feats, layer0 epilogue fused (isqrt+bias+BN stats)
// bufA -> bufB
__global__ void k_gather64_l0(const float* __restrict__ bias) {
    __shared__ float s_s[64], s_q[64];
    if (threadIdx.x < 64) { s_s[threadIdx.x] = 0.0f; s_q[threadIdx.x] = 0.0f; }
    __syncthreads();
    int node = blockIdx.x * 8 + (threadIdx.x >> 5);
    int lane = threadIdx.x & 31;
    if (node < GN) {
        int beg = g_row[node], end = g_row[node + 1];
        float ax = 0.0f, ay = 0.0f;
        for (int e = beg; e < end; e++) {
            int s = __ldg(&g_col[e]);
            float2 v = *(const float2*)&g_bufA[s * 64 + 2 * lane];
            ax += v.x; ay += v.y;
        }
        float isq = g_in_isqrt[node];
        float v0 = ax * isq + __ldg(&bias[2 * lane]);
        float v1 = ay * isq + __ldg(&bias[2 * lane + 1]);
        *(float2*)&g_bufB[node * 64 + 2 * lane] = make_float2(v0, v1);
        atomicAdd(&s_s[2 * lane], v0);      atomicAdd(&s_s[2 * lane + 1], v1);
        atomicAdd(&s_q[2 * lane], v0 * v0); atomicAdd(&s_q[2 * lane + 1], v1 * v1);
    }
    __syncthreads();
    if (threadIdx.x < 64) {
        atomicAdd(&g_stats[threadIdx.x],      s_s[threadIdx.x]);
        atomicAdd(&g_stats[64 + threadIdx.x], s_q[threadIdx.x]);
    }
}

// ---------------- finalize BN ----------------
__global__ void k_finalize_bn(const float* __restrict__ gamma,
                              const float* __restrict__ beta) {
    int f = threadIdx.x;
    if (f >= 64) return;
    float inv_n = 1.0f / (float)GN;
    float mu = g_stats[f] * inv_n;
    float var = g_stats[64 + f] * inv_n - mu * mu;
    float rstd = rsqrtf(var + EPS);
    float sc = __ldg(&gamma[f]) * rstd;
    g_stats[128 + f] = sc;
    g_stats[192 + f] = __ldg(&beta[f]) - mu * sc;
}

// ---------------- gather64 with fused BN+ReLU+out_isqrt on SOURCE elements
// reads y0 from bufB, applies t(x)=max(sc*x+sh,0)*out_isqrt[src], aggregates -> bufA
__global__ void k_gather64_bn() {
    // fold: zero stats accumulators for the next stats pass
    if (blockIdx.x == 0 && threadIdx.x < 128) g_stats[threadIdx.x] = 0.0f;
    int node = blockIdx.x * 8 + (threadIdx.x >> 5);
    int lane = threadIdx.x & 31;
    if (node >= GN) return;
    float sc0 = g_stats[128 + 2 * lane], sc1 = g_stats[128 + 2 * lane + 1];
    float sh0 = g_stats[192 + 2 * lane], sh1 = g_stats[192 + 2 * lane + 1];
    int beg = g_row[node], end = g_row[node + 1];
    float ax = 0.0f, ay = 0.0f;
    for (int e = beg; e < end; e++) {
        int s = __ldg(&g_col[e]);
        float os = __ldg(&g_out_isqrt[s]);
        float2 v = *(const float2*)&g_bufB[s * 64 + 2 * lane];
        ax += fmaxf(v.x * sc0 + sh0, 0.0f) * os;
        ay += fmaxf(v.y * sc1 + sh1, 0.0f) * os;
    }
    *(float2*)&g_bufA[node * 64 + 2 * lane] = make_float2(ax, ay);
}

// ---------------- GEMM1: bufA @ W1 then *in_isqrt + b1 -> bufB; BN stats --
// 128 nodes x 64 cols per block; thread = 8 nodes x 4 cols
__global__ void k_gemm1_stats(const float* __restrict__ W,
                              const float* __restrict__ bias) {
    __shared__ float sAT[16][132];
    __shared__ float sW[16][64];
    __shared__ float s_isq[128];
    __shared__ float s_s[64], s_q[64];
    int base = blockIdx.x * 128;
    for (int i = threadIdx.x; i < 128; i += 256) {
        int node = base + i;
        s_isq[i] = (node < GN) ? g_in_isqrt[node] : 0.0f;
    }
    if (threadIdx.x < 64) { s_s[threadIdx.x] = 0.0f; s_q[threadIdx.x] = 0.0f; }
    int cgi = threadIdx.x & 15;
    int ngi = threadIdx.x >> 4;
    int cg = cgi * 4;
    float acc[8][4] = {};
    for (int kb = 0; kb < 4; kb++) {
        __syncthreads();
        #pragma unroll
        for (int it = 0; it < 2; it++) {
            int task = threadIdx.x + 256 * it;
            int node = task >> 2, k4 = task & 3;
            int gnode = base + node;
            float4 v = make_float4(0.f, 0.f, 0.f, 0.f);
            if (gnode < GN)
                v = *(const float4*)&g_bufA[gnode * 64 + kb * 16 + k4 * 4];
            sAT[4 * k4 + 0][node] = v.x;
            sAT[4 * k4 + 1][node] = v.y;
            sAT[4 * k4 + 2][node] = v.z;
            sAT[4 * k4 + 3][node] = v.w;
        }
        {
            int kk = threadIdx.x >> 4, c4 = threadIdx.x & 15;
            *(float4*)&sW[kk][c4 * 4] =
                __ldg((const float4*)&W[(kb * 16 + kk) * 64 + c4 * 4]);
        }
        __syncthreads();
        #pragma unroll
        for (int kk = 0; kk < 16; kk++) {
            float4 a0 = *(const float4*)&sAT[kk][ngi * 8];
            float4 a1 = *(const float4*)&sAT[kk][ngi * 8 + 4];
            float4 w  = *(const float4*)&sW[kk][cg];
            float av[8] = {a0.x, a0.y, a0.z, a0.w, a1.x, a1.y, a1.z, a1.w};
            #pragma unroll
            for (int i = 0; i < 8; i++) {
                acc[i][0] += av[i] * w.x;
                acc[i][1] += av[i] * w.y;
                acc[i][2] += av[i] * w.z;
                acc[i][3] += av[i] * w.w;
            }
        }
    }
    float4 bv = __ldg((const float4*)&bias[cg]);
    float ls[4] = {}, lq[4] = {};
    #pragma unroll
    for (int i = 0; i < 8; i++) {
        int node = base + ngi * 8 + i;
        if (node < GN) {
            float is = s_isq[ngi * 8 + i];
            float v0 = acc[i][0] * is + bv.x;
            float v1 = acc[i][1] * is + bv.y;
            float v2 = acc[i][2] * is + bv.z;
            float v3 = acc[i][3] * is + bv.w;
            *(float4*)&g_bufB[node * 64 + cg] = make_float4(v0, v1, v2, v3);
            ls[0] += v0; lq[0] += v0 * v0;
            ls[1] += v1; lq[1] += v1 * v1;
            ls[2] += v2; lq[2] += v2 * v2;
            ls[3] += v3; lq[3] += v3 * v3;
        }
    }
    #pragma unroll
    for (int j = 0; j < 4; j++) {
        atomicAdd(&s_s[cg + j], ls[j]);
        atomicAdd(&s_q[cg + j], lq[j]);
    }
    __syncthreads();
    if (threadIdx.x < 64) {
        atomicAdd(&g_stats[threadIdx.x],      s_s[threadIdx.x]);
        atomicAdd(&g_stats[64 + threadIdx.x], s_q[threadIdx.x]);
    }
}

// ---------------- GEMM2: t1(bufB) @ W2  [64 -> 47] -> bufA (stride 64) -----
// BN1+ReLU+out_isqrt applied during transposed staging; cols padded to 64
__global__ void k_gemm2_bn(const float* __restrict__ W) {
    __shared__ float sAT[16][132];
    __shared__ float sW[16][64];
    __shared__ float s_os[128];
    __shared__ float s_sc[64], s_sh[64];
    int base = blockIdx.x * 128;
    for (int i = threadIdx.x; i < 128; i += 256) {
        int node = base + i;
        s_os[i] = (node < GN) ? g_out_isqrt[node] : 0.0f;
    }
    if (threadIdx.x < 64) {
        s_sc[threadIdx.x] = g_stats[128 + threadIdx.x];
        s_sh[threadIdx.x] = g_stats[192 + threadIdx.x];
    }
    int cgi = threadIdx.x & 15;
    int ngi = threadIdx.x >> 4;
    int cg = cgi * 4;
    float acc[8][4] = {};
    for (int kb = 0; kb < 4; kb++) {
        __syncthreads();
        #pragma unroll
        for (int it = 0; it < 2; it++) {
            int task = threadIdx.x + 256 * it;
            int node = task >> 2, k4 = task & 3;
            int gnode = base + node;
            float4 v = make_float4(0.f, 0.f, 0.f, 0.f);
            if (gnode < GN)
                v = *(const float4*)&g_bufB[gnode * 64 + kb * 16 + k4 * 4];
            float os = s_os[node];
            int k = kb * 16 + 4 * k4;
            sAT[4 * k4 + 0][node] = fmaxf(v.x * s_sc[k]     + s_sh[k],     0.0f) * os;
            sAT[4 * k4 + 1][node] = fmaxf(v.y * s_sc[k + 1] + s_sh[k + 1], 0.0f) * os;
            sAT[4 * k4 + 2][node] = fmaxf(v.z * s_sc[k + 2] + s_sh[k + 2], 0.0f) * os;
            sAT[4 * k4 + 3][node] = fmaxf(v.w * s_sc[k + 3] + s_sh[k + 3], 0.0f) * os;
        }
        // stage W2 [64x47] panel with zero-pad to 64 cols (scalar loads)
        #pragma unroll
        for (int it = 0; it < 4; it++) {
            int i = threadIdx.x + 256 * it;       // 1024 = 16 kk x 64 c
            int kk = i >> 6, c = i & 63;
            float w = 0.0f;
            if (c < 47) w = __ldg(&W[(kb * 16 + kk) * 47 + c]);
            sW[kk][c] = w;
        }
        __syncthreads();
        #pragma unroll
        for (int kk = 0; kk < 16; kk++) {
            float4 a0 = *(const float4*)&sAT[kk][ngi * 8];
            float4 a1 = *(const float4*)&sAT[kk][ngi * 8 + 4];
            float4 w  = *(const float4*)&sW[kk][cg];
            float av[8] = {a0.x, a0.y, a0.z, a0.w, a1.x, a1.y, a1.z, a1.w};
            #pragma unroll
            for (int i = 0; i < 8; i++) {
                acc[i][0] += av[i] * w.x;
                acc[i][1] += av[i] * w.y;
                acc[i][2] += av[i] * w.z;
                acc[i][3] += av[i] * w.w;
            }
        }
    }
    if (cg < 47) {
        #pragma unroll
        for (int i = 0; i < 8; i++) {
            int node = base + ngi * 8 + i;
            if (node < GN) {
                if (cg + 3 < 47) {
                    *(float4*)&g_bufA[node * 64 + cg] =
                        make_float4(acc[i][0], acc[i][1], acc[i][2], acc[i][3]);
                } else {
                    #pragma unroll
                    for (int j = 0; j < 4; j++)
                        if (cg + j < 47) g_bufA[node * 64 + cg + j] = acc[i][j];
                }
            }
        }
    }
}

// ---------------- gather, 47 feats + final epilogue: bufA -> out ----------
__global__ void k_gather47(const float* __restrict__ b2,
                           float* __restrict__ out) {
    int node = blockIdx.x * 8 + (threadIdx.x >> 5);
    int lane = threadIdx.x & 31;
    if (node >= GN) return;
    int beg = g_row[node], end = g_row[node + 1];
    int f = 2 * lane;
    float ax = 0.0f, ay = 0.0f;
    if (f < 46) {                    // lanes 0..22: pair
        for (int e = beg; e < end; e++) {
            int s = __ldg(&g_col[e]);
            float2 v = *(const float2*)&g_bufA[s * 64 + f];
            ax += v.x; ay += v.y;
        }
        float isq = g_in_isqrt[node];
        out[node * 47 + f]     = ax * isq + __ldg(&b2[f]);
        out[node * 47 + f + 1] = ay * isq + __ldg(&b2[f + 1]);
    } else if (f == 46) {            // lane 23: single feat 46
        for (int e = beg; e < end; e++) {
            int s = __ldg(&g_col[e]);
            ax += g_bufA[s * 64 + 46];
        }
        out[node * 47 + 46] = ax * g_in_isqrt[node] + __ldg(&b2[46]);
    }
}

// ============================================================================
extern "C" void kernel_launch(void* const* d_in, const int* in_sizes, int n_in,
                              void* d_out, int out_size) {
    const float* feat = (const float*)d_in[0];
    const int*   src  = (const int*)d_in[1];    // int32 (jax x64 disabled)
    const int*   dst  = (const int*)d_in[2];
    const float* W0 = (const float*)d_in[3];
    const float* b0 = (const float*)d_in[4];
    const float* W1 = (const float*)d_in[5];
    const float* b1 = (const float*)d_in[6];
    const float* W2 = (const float*)d_in[7];
    const float* b2 = (const float*)d_in[8];
    const float* gamma0 = (const float*)d_in[9];
    const float* beta0  = (const float*)d_in[10];
    const float* gamma1 = (const float*)d_in[11];
    const float* beta1  = (const float*)d_in[12];
    float* out = (float*)d_out;

    const int GB = 12500;   // gather blocks: 8 nodes each
    const int MB = (GN + 127) / 128;   // gemm blocks: 128 nodes each

    // ---- CSR build + degree isqrt ----
    k_zero_int<<<(GN + 255) / 256, 256>>>();
    k_count<<<(GE + 255) / 256, 256>>>(src, dst);
    k_scan_part<<<NB_SCAN, 1024>>>();
    k_scan_mid<<<1, 32>>>();
    k_scan_final<<<NB_SCAN, 1024>>>();      // also computes isqrt + fill cursors
    k_fill<<<(GE + 255) / 256, 256>>>(src, dst);

    // ---- layer 0: matmul (128 -> 64), gather w/ fused epilogue ----
    k_gemm0<<<MB, 256>>>(feat, W0);              // feat -> bufA (+zero stats)
    k_gather64_l0<<<GB, 256>>>(b0);              // bufA -> bufB (y0 + stats)
    k_finalize_bn<<<1, 64>>>(gamma0, beta0);

    // ---- layer 1: gather w/ fused BN0 transform, matmul (64 -> 64) ----
    k_gather64_bn<<<GB, 256>>>();                // bufB -> bufA (+zero stats)
    k_gemm1_stats<<<MB, 256>>>(W1, b1);          // bufA -> bufB (y1 + stats)
    k_finalize_bn<<<1, 64>>>(gamma1, beta1);

    // ---- layer 2: matmul w/ fused BN1 transform (64 -> 47), gather ----
    k_gemm2_bn<<<MB, 256>>>(W2);                 // bufB -> bufA (stride 64)
    k_gather47<<<GB, 256>>>(b2, out);            // bufA -> out
}